// round 1
// baseline (speedup 1.0000x reference)
#include <cuda_runtime.h>

#define NV 256
#define MANG 180
#define LPB 8

// Scratch (static device globals — no runtime allocation)
__device__ float2 g_F[NV * NV * NV];        // centered 3D FFT of volume (134 MB)
__device__ float2 g_S[MANG * NV * NV];      // sampled Fourier slices (94 MB)

// ---------------------------------------------------------------------------
// Batched 256-point centered FFT (radix-2 DIF, bit-reversal folded into store)
// Centered transform for even n: out[k] = (-1)^k * FFT[(-1)^j * in[j]][k]
// SIGN = -1 forward, +1 inverse. INV applies 1/256 scaling.
// ls = log2(element stride along the transform axis).
// Line l base offset = ((l >> ls) << (ls+8)) + (l & (stride-1)).
// ---------------------------------------------------------------------------
template <int SIGN, bool INV>
__global__ void __launch_bounds__(256) fft256(const float2* __restrict__ in,
                                              float2* __restrict__ out,
                                              int ls) {
    __shared__ float2 sm[LPB][NV];
    const int tid  = threadIdx.x;
    const int warp = tid >> 5;
    const int lane = tid & 31;
    const long l0  = (long)blockIdx.x * LPB;

    long base0;
    if (ls == 0) {
        base0 = l0 << 8;
    } else {
        base0 = ((l0 >> ls) << (ls + 8)) + (l0 & ((1L << ls) - 1));
    }

    // ---- load (with (-1)^j input sign) ----
    if (ls == 0) {
        for (int idx = tid; idx < LPB * NV; idx += 256) {
            int j = idx & 255;
            float2 v = in[base0 + idx];
            float s = (j & 1) ? -1.0f : 1.0f;
            sm[idx >> 8][j] = make_float2(v.x * s, v.y * s);
        }
    } else {
        for (int idx = tid; idx < LPB * NV; idx += 256) {
            int b = idx & (LPB - 1);
            int j = idx >> 3;
            float2 v = in[base0 + b + ((long)j << ls)];
            float s = (j & 1) ? -1.0f : 1.0f;
            sm[b][j] = make_float2(v.x * s, v.y * s);
        }
    }
    __syncthreads();

    // ---- 8 radix-2 DIF stages; warp w owns line w ----
    float2* line = sm[warp];
#pragma unroll
    for (int stg = 0; stg < 8; stg++) {
        const int hs = 7 - stg;
        const int h  = 1 << hs;
#pragma unroll
        for (int q = 0; q < 4; q++) {
            int t  = q * 32 + lane;
            int g  = t >> hs;
            int j  = t & (h - 1);
            int i0 = (g << (hs + 1)) + j;
            int i1 = i0 + h;
            float2 a = line[i0];
            float2 b = line[i1];
            line[i0] = make_float2(a.x + b.x, a.y + b.y);
            float dr = a.x - b.x;
            float di = a.y - b.y;
            float sw, cw;
            sincospif((float)(SIGN * j) / (float)h, &sw, &cw);
            line[i1] = make_float2(dr * cw - di * sw, dr * sw + di * cw);
        }
        __syncwarp();
    }
    __syncthreads();

    // ---- store (bit-reversed read, (-1)^k output sign, optional 1/n) ----
    const float scale = INV ? (1.0f / 256.0f) : 1.0f;
    if (ls == 0) {
        for (int idx = tid; idx < LPB * NV; idx += 256) {
            int k = idx & 255;
            float2 v = sm[idx >> 8][__brev((unsigned)k) >> 24];
            float s = (k & 1) ? -scale : scale;
            out[base0 + idx] = make_float2(v.x * s, v.y * s);
        }
    } else {
        for (int idx = tid; idx < LPB * NV; idx += 256) {
            int b = idx & (LPB - 1);
            int k = idx >> 3;
            float2 v = sm[b][__brev((unsigned)k) >> 24];
            float s = (k & 1) ? -scale : scale;
            out[base0 + b + ((long)k << ls)] = make_float2(v.x * s, v.y * s);
        }
    }
}

// ---------------------------------------------------------------------------
// Fourier-slice trilinear sampling.
// thread = iu, blockIdx.x = iv, blockIdx.y = m (angle).
// pos = (iu-128)*e_u + (iv-128)*e_v + 128  (exact: fr*n = iu-128 in f32)
// e_u = (ct, st, 0); e_v = (-st*cp, ct*cp, sp)
// ---------------------------------------------------------------------------
__global__ void __launch_bounds__(256) sample_kernel(const float2* __restrict__ F,
                                                     const float* __restrict__ theta,
                                                     const float* __restrict__ tilt,
                                                     float2* __restrict__ S) {
    const int iu = threadIdx.x;
    const int iv = blockIdx.x;
    const int m  = blockIdx.y;

    float th = theta[m];
    float st, ct;
    sincosf(th, &st, &ct);
    float tl = *tilt;
    float sp, cp;
    sincosf(tl, &sp, &cp);

    float u = (float)(iu - 128);
    float v = (float)(iv - 128);

    float px = u * ct + v * (-st * cp) + 128.0f;   // dim0 (x)
    float py = u * st + v * (ct * cp) + 128.0f;    // dim1 (y)
    float pz = v * sp + 128.0f;                    // dim2 (z)

    float fx0 = floorf(px), fy0 = floorf(py), fz0 = floorf(pz);
    float fx = px - fx0, fy = py - fy0, fz = pz - fz0;
    int x0 = (int)fx0, y0 = (int)fy0, z0 = (int)fz0;

    float2 acc = make_float2(0.0f, 0.0f);
#pragma unroll
    for (int dx = 0; dx < 2; dx++) {
        int X = x0 + dx;
        float wx = dx ? fx : (1.0f - fx);
#pragma unroll
        for (int dy = 0; dy < 2; dy++) {
            int Y = y0 + dy;
            float wy = dy ? fy : (1.0f - fy);
#pragma unroll
            for (int dz = 0; dz < 2; dz++) {
                int Z = z0 + dz;
                float wz = dz ? fz : (1.0f - fz);
                if ((unsigned)X < 256u && (unsigned)Y < 256u && (unsigned)Z < 256u) {
                    float w = wx * wy * wz;
                    float2 val = F[(((long)X << 8) + Y << 8) + Z];
                    acc.x += w * val.x;
                    acc.y += w * val.y;
                }
            }
        }
    }
    S[((((long)m << 8) + iv) << 8) + iu] = acc;
}

// ---------------------------------------------------------------------------
extern "C" void kernel_launch(void* const* d_in, const int* in_sizes, int n_in,
                              void* d_out, int out_size) {
    const float2* w     = (const float2*)d_in[0];   // (256,256,256,2) f32
    const float*  theta = (const float*)d_in[1];    // (180,)
    const float*  tilt  = (const float*)d_in[2];    // scalar
    float2* out = (float2*)d_out;                   // (180,256,256,2) f32

    float2 *F, *S;
    cudaGetSymbolAddress((void**)&F, g_F);
    cudaGetSymbolAddress((void**)&S, g_S);

    // Centered forward 3D FFT: z (stride 1), y (stride 256), x (stride 65536)
    fft256<-1, false><<<65536 / LPB, 256>>>(w, F, 0);
    fft256<-1, false><<<65536 / LPB, 256>>>(F, F, 8);
    fft256<-1, false><<<65536 / LPB, 256>>>(F, F, 16);

    // Fourier-slice trilinear sampling: (M, n, n)
    dim3 gs(NV, MANG);
    sample_kernel<<<gs, 256>>>(F, theta, tilt, S);

    // Centered inverse 2D FFT per angle: iu (stride 1), then iv (stride 256)
    fft256<1, true><<<(MANG * NV) / LPB, 256>>>(S, S, 0);
    fft256<1, true><<<(MANG * NV) / LPB, 256>>>(S, out, 8);
}

// round 2
// speedup vs baseline: 1.7626x; 1.7626x over previous
#include <cuda_runtime.h>

#define NV 256
#define MANG 180
#define LPB 8
#define PIDX(j) ((j) + ((j) >> 3))
#define LSZ 288

// Scratch (static device globals — no runtime allocation)
__device__ float2 g_F[NV * NV * NV];        // centered 3D FFT of volume
__device__ float2 g_S[MANG * NV * NV];      // sampled Fourier slices

__device__ __forceinline__ float2 cmulf(float2 a, float2 b) {
    return make_float2(a.x * b.x - a.y * b.y, a.x * b.y + a.y * b.x);
}

// ---------------------------------------------------------------------------
// Batched 256-point centered FFT.
// Decomposition: 256 = 8 (registers, radix-2 DIF x3) x 32 (lanes, shuffle DIF x5).
// Twiddles from a 256-entry shared table e^{SIGN*i*pi*t/128}.
// Centered transform: (-1)^j on input (= (-1)^lane), (-1)^k on output
// (= sign of reg>>2), digit-reversed output order folded into shared store.
// SIGN=-1 fwd, +1 inv (with 1/256 scale). ls = log2(element stride).
// ---------------------------------------------------------------------------
template <int SIGN, bool INV>
__global__ void __launch_bounds__(256) fft256(const float2* __restrict__ in,
                                              float2* __restrict__ out,
                                              int ls) {
    __shared__ float2 sm[LPB][LSZ];
    __shared__ float2 tw[256];
    const int tid  = threadIdx.x;
    const int warp = tid >> 5;
    const int lane = tid & 31;
    const long l0  = (long)blockIdx.x * LPB;

    long base0 = (ls == 0) ? (l0 << 8)
               : (((l0 >> ls) << (ls + 8)) + (l0 & ((1L << ls) - 1)));

    // twiddle table: tw[t] = e^{SIGN * i*pi*t/128}
    {
        float s, c;
        sincospif((float)tid * (1.0f / 128.0f), &s, &c);
        tw[tid] = make_float2(c, (float)SIGN * s);
    }

    // ---- cooperative staged load (coalesced 64B segments for strided axes) ----
    if (ls == 0) {
        for (int idx = tid; idx < LPB * NV; idx += 256)
            sm[idx >> 8][PIDX(idx & 255)] = in[base0 + idx];
    } else {
        for (int idx = tid; idx < LPB * NV; idx += 256) {
            int b = idx & (LPB - 1);
            int j = idx >> 3;
            sm[b][PIDX(j)] = in[base0 + b + ((long)j << ls)];
        }
    }
    __syncthreads();

    // ---- load line into registers: x[r] = in[r*32 + lane] * (-1)^lane ----
    float2 x[8];
    const float insgn = (lane & 1) ? -1.0f : 1.0f;
#pragma unroll
    for (int r = 0; r < 8; r++) {
        float2 v = sm[warp][PIDX(r * 32 + lane)];
        x[r] = make_float2(v.x * insgn, v.y * insgn);
    }

    // ---- radix-8 DIF over registers (constant twiddles) ----
    const float SG = (float)SIGN;
    const float C7 = 0.70710678118654752f;
#define BTF(A, B, TR, TI)                                          \
    {                                                              \
        float dr = (A).x - (B).x, di = (A).y - (B).y;              \
        (A).x += (B).x; (A).y += (B).y;                            \
        (B).x = dr * (TR) - di * (TI);                             \
        (B).y = dr * (TI) + di * (TR);                             \
    }
    // stage h=4: tw_j = e^{SIGN i pi j/4}
    BTF(x[0], x[4], 1.0f, 0.0f);
    BTF(x[1], x[5], C7, SG * C7);
    BTF(x[2], x[6], 0.0f, SG);
    BTF(x[3], x[7], -C7, SG * C7);
    // stage h=2
    BTF(x[0], x[2], 1.0f, 0.0f);
    BTF(x[1], x[3], 0.0f, SG);
    BTF(x[4], x[6], 1.0f, 0.0f);
    BTF(x[5], x[7], 0.0f, SG);
    // stage h=1
    BTF(x[0], x[1], 1.0f, 0.0f);
    BTF(x[2], x[3], 1.0f, 0.0f);
    BTF(x[4], x[5], 1.0f, 0.0f);
    BTF(x[6], x[7], 1.0f, 0.0f);
#undef BTF

    // reg r now holds k1 = brev3(r)
    const int k1tab[8] = {0, 4, 2, 6, 1, 5, 3, 7};

    // ---- inter-factor twiddle: x[r] *= W_256^{lane * k1} ----
#pragma unroll
    for (int r = 1; r < 8; r++) {
        x[r] = cmulf(x[r], tw[(lane * k1tab[r]) & 255]);
    }

    // ---- radix-32 DIF across lanes via shuffles (5 stages) ----
#pragma unroll
    for (int s = 4; s >= 0; s--) {
        const int h = 1 << s;
        const int j = lane & (h - 1);
        const float2 w = tw[j << (7 - s)];
        const bool hi = (lane & h) != 0;
#pragma unroll
        for (int r = 0; r < 8; r++) {
            float2 o;
            o.x = __shfl_xor_sync(0xffffffffu, x[r].x, h);
            o.y = __shfl_xor_sync(0xffffffffu, x[r].y, h);
            if (hi) {
                float2 d = make_float2(o.x - x[r].x, o.y - x[r].y);
                x[r] = cmulf(d, w);
            } else {
                x[r].x += o.x;
                x[r].y += o.y;
            }
        }
    }

    // ---- store to shared in natural output order with (-1)^k and scale ----
    const float scale = INV ? (1.0f / 256.0f) : 1.0f;
    const int p = (int)(__brev((unsigned)lane) >> 27);  // brev5(lane) = k2
#pragma unroll
    for (int r = 0; r < 8; r++) {
        int k = k1tab[r] + 8 * p;
        float sg = ((r >> 2) & 1) ? -scale : scale;     // (-1)^k, k&1 = brev3(r)&1
        sm[warp][PIDX(k)] = make_float2(x[r].x * sg, x[r].y * sg);
    }
    __syncthreads();

    // ---- cooperative staged store ----
    if (ls == 0) {
        for (int idx = tid; idx < LPB * NV; idx += 256)
            out[base0 + idx] = sm[idx >> 8][PIDX(idx & 255)];
    } else {
        for (int idx = tid; idx < LPB * NV; idx += 256) {
            int b = idx & (LPB - 1);
            int k = idx >> 3;
            out[base0 + b + ((long)k << ls)] = sm[b][PIDX(k)];
        }
    }
}

// ---------------------------------------------------------------------------
// Fourier-slice trilinear sampling, iv-major lanes (z-contiguous gathers).
// block (32, 8): tx = iv within tile, ty = iu within tile.
// grid (8, 32, 180).
// ---------------------------------------------------------------------------
__global__ void __launch_bounds__(256) sample_kernel(const float2* __restrict__ F,
                                                     const float* __restrict__ theta,
                                                     const float* __restrict__ tilt,
                                                     float2* __restrict__ S) {
    __shared__ float2 tile[8][33];
    const int tx = threadIdx.x;           // iv offset
    const int ty = threadIdx.y;           // iu offset
    const int bv = blockIdx.x * 32;
    const int bu = blockIdx.y * 8;
    const int m  = blockIdx.z;
    const int iv = bv + tx;
    const int iu = bu + ty;

    float st, ct;
    sincosf(theta[m], &st, &ct);
    float sp, cp;
    sincosf(*tilt, &sp, &cp);

    float u = (float)(iu - 128);
    float v = (float)(iv - 128);

    float px = u * ct + v * (-st * cp) + 128.0f;   // dim0 (x)
    float py = u * st + v * (ct * cp) + 128.0f;    // dim1 (y)
    float pz = v * sp + 128.0f;                    // dim2 (z)

    float fx0 = floorf(px), fy0 = floorf(py), fz0 = floorf(pz);
    float fx = px - fx0, fy = py - fy0, fz = pz - fz0;
    int x0 = (int)fx0, y0 = (int)fy0, z0 = (int)fz0;

    float2 acc = make_float2(0.0f, 0.0f);
#pragma unroll
    for (int dx = 0; dx < 2; dx++) {
        int X = x0 + dx;
        float wx = dx ? fx : (1.0f - fx);
#pragma unroll
        for (int dy = 0; dy < 2; dy++) {
            int Y = y0 + dy;
            float wy = wx * (dy ? fy : (1.0f - fy));
#pragma unroll
            for (int dz = 0; dz < 2; dz++) {
                int Z = z0 + dz;
                float wz = wy * (dz ? fz : (1.0f - fz));
                if ((unsigned)X < 256u && (unsigned)Y < 256u && (unsigned)Z < 256u) {
                    float2 val = F[((((long)X << 8) + Y) << 8) + Z];
                    acc.x += wz * val.x;
                    acc.y += wz * val.y;
                }
            }
        }
    }

    // transpose through shared so stores are 64B-coalesced along iu
    tile[ty][tx] = acc;
    __syncthreads();
    int t = ty * 32 + tx;
    int iu2 = t & 7;
    int iv2 = t >> 3;
    S[(((long)m * 256 + (bv + iv2)) << 8) + bu + iu2] = tile[iu2][iv2];
}

// ---------------------------------------------------------------------------
extern "C" void kernel_launch(void* const* d_in, const int* in_sizes, int n_in,
                              void* d_out, int out_size) {
    const float2* w     = (const float2*)d_in[0];   // (256,256,256,2) f32
    const float*  theta = (const float*)d_in[1];    // (180,)
    const float*  tilt  = (const float*)d_in[2];    // scalar
    float2* out = (float2*)d_out;                   // (180,256,256,2) f32

    float2 *F, *S;
    cudaGetSymbolAddress((void**)&F, g_F);
    cudaGetSymbolAddress((void**)&S, g_S);

    // Centered forward 3D FFT: z (stride 1), y (stride 256), x (stride 65536)
    fft256<-1, false><<<65536 / LPB, 256>>>(w, F, 0);
    fft256<-1, false><<<65536 / LPB, 256>>>(F, F, 8);
    fft256<-1, false><<<65536 / LPB, 256>>>(F, F, 16);

    // Fourier-slice trilinear sampling
    dim3 gs(NV / 32, NV / 8, MANG);
    dim3 bs(32, 8);
    sample_kernel<<<gs, bs>>>(F, theta, tilt, S);

    // Centered inverse 2D FFT per angle: iu (stride 1), then iv (stride 256)
    fft256<1, true><<<(MANG * NV) / LPB, 256>>>(S, S, 0);
    fft256<1, true><<<(MANG * NV) / LPB, 256>>>(S, out, 8);
}

// round 3
// speedup vs baseline: 2.0852x; 1.1830x over previous
#include <cuda_runtime.h>

#define NV 256
#define MANG 180
#define PIDX(j) ((j) + ((j) >> 3))

// Scratch (static device globals — no runtime allocation)
__device__ float2 g_F[NV * NV * NV];        // centered 3D FFT of volume
__device__ float2 g_S[MANG * NV * NV];      // slice FFT intermediate T[m][iu][ka]

__device__ __forceinline__ float2 cmulf(float2 a, float2 b) {
    return make_float2(a.x * b.x - a.y * b.y, a.x * b.y + a.y * b.x);
}

// ---------------------------------------------------------------------------
// 256-pt FFT core: 8 regs/lane. radix-2^3 in regs + twiddle + radix-32 shuffle.
// On exit reg r, lane holds bin k = brev3(r) + 8*brev5(lane).
// tw[t] = e^{SIGN*i*pi*t/128}.
// ---------------------------------------------------------------------------
template <int SIGN>
__device__ __forceinline__ void fft_core(float2 x[8], int lane, const float2* tw) {
    const float SG = (float)SIGN;
    const float C7 = 0.70710678118654752f;
#define BTF(A, B, TR, TI)                                          \
    {                                                              \
        float dr = (A).x - (B).x, di = (A).y - (B).y;              \
        (A).x += (B).x; (A).y += (B).y;                            \
        (B).x = dr * (TR) - di * (TI);                             \
        (B).y = dr * (TI) + di * (TR);                             \
    }
    BTF(x[0], x[4], 1.0f, 0.0f);
    BTF(x[1], x[5], C7, SG * C7);
    BTF(x[2], x[6], 0.0f, SG);
    BTF(x[3], x[7], -C7, SG * C7);
    BTF(x[0], x[2], 1.0f, 0.0f);
    BTF(x[1], x[3], 0.0f, SG);
    BTF(x[4], x[6], 1.0f, 0.0f);
    BTF(x[5], x[7], 0.0f, SG);
    BTF(x[0], x[1], 1.0f, 0.0f);
    BTF(x[2], x[3], 1.0f, 0.0f);
    BTF(x[4], x[5], 1.0f, 0.0f);
    BTF(x[6], x[7], 1.0f, 0.0f);
#undef BTF
    const int k1tab[8] = {0, 4, 2, 6, 1, 5, 3, 7};
#pragma unroll
    for (int r = 1; r < 8; r++)
        x[r] = cmulf(x[r], tw[(lane * k1tab[r]) & 255]);
#pragma unroll
    for (int s = 4; s >= 0; s--) {
        const int h = 1 << s;
        const int j = lane & (h - 1);
        const float2 w = tw[j << (7 - s)];
        const bool hi = (lane & h) != 0;
#pragma unroll
        for (int r = 0; r < 8; r++) {
            float2 o;
            o.x = __shfl_xor_sync(0xffffffffu, x[r].x, h);
            o.y = __shfl_xor_sync(0xffffffffu, x[r].y, h);
            if (hi) {
                float2 d = make_float2(o.x - x[r].x, o.y - x[r].y);
                x[r] = cmulf(d, w);
            } else {
                x[r].x += o.x;
                x[r].y += o.y;
            }
        }
    }
}

// ---------------------------------------------------------------------------
// Contiguous-axis batched centered FFT: 8 lines/block, in/out contiguous.
// ---------------------------------------------------------------------------
template <int SIGN, bool INV>
__global__ void __launch_bounds__(256) fft256c(const float2* __restrict__ in,
                                               float2* __restrict__ out) {
    __shared__ float2 sm[8][288];
    __shared__ float2 tw[256];
    const int tid  = threadIdx.x;
    const int warp = tid >> 5;
    const int lane = tid & 31;
    const unsigned base = blockIdx.x * 2048u;

    {
        float s, c;
        sincospif((float)tid * (1.0f / 128.0f), &s, &c);
        tw[tid] = make_float2(c, (float)SIGN * s);
    }
    for (int idx = tid; idx < 2048; idx += 256)
        sm[idx >> 8][PIDX(idx & 255)] = in[base + idx];
    __syncthreads();

    float2 x[8];
    const float insgn = (lane & 1) ? -1.0f : 1.0f;
#pragma unroll
    for (int r = 0; r < 8; r++) {
        float2 v = sm[warp][PIDX(r * 32 + lane)];
        x[r] = make_float2(v.x * insgn, v.y * insgn);
    }
    fft_core<SIGN>(x, lane, tw);

    const float scale = INV ? (1.0f / 256.0f) : 1.0f;
    const int k1tab[8] = {0, 4, 2, 6, 1, 5, 3, 7};
    const int p = (int)(__brev((unsigned)lane) >> 27);
#pragma unroll
    for (int r = 0; r < 8; r++) {
        int k = k1tab[r] + 8 * p;
        float sg = ((r >> 2) & 1) ? -scale : scale;
        sm[warp][PIDX(k)] = make_float2(x[r].x * sg, x[r].y * sg);
    }
    __syncthreads();
    for (int idx = tid; idx < 2048; idx += 256)
        out[base + idx] = sm[idx >> 8][PIDX(idx & 255)];
}

// ---------------------------------------------------------------------------
// Strided-axis batched centered FFT: 16 lines/block (128B gmem segments).
// Shared layout idx(j,b) = j*17 + (b ^ (j>>4)) — conflict-free in all phases.
// ZFILT: skip blocks whose z-range (z = line & 255) is never sampled.
// TRANSP: write lines contiguously (out[line*256 + k]) instead of strided.
// ---------------------------------------------------------------------------
template <int SIGN, bool INV, bool ZFILT, bool TRANSP>
__global__ void __launch_bounds__(256) fft256s(const float2* __restrict__ in,
                                               float2* __restrict__ out,
                                               int lsi, const float* tilt) {
    __shared__ float2 sm[256 * 17];
    __shared__ float2 tw[256];
    const int tid  = threadIdx.x;
    const int warp = tid >> 5;
    const int lane = tid & 31;
    const unsigned l0 = blockIdx.x * 16u;

    if (ZFILT) {
        float a = 128.0f * fabsf(sinf(*tilt));
        int zlo = (int)floorf(126.0f - a);
        int zhi = (int)ceilf(130.0f + a);
        int z0 = (int)(l0 & 255u);
        if (z0 > zhi || z0 + 15 < zlo) return;
    }

    {
        float s, c;
        sincospif((float)tid * (1.0f / 128.0f), &s, &c);
        tw[tid] = make_float2(c, (float)SIGN * s);
    }

    const unsigned basei = ((l0 >> lsi) << (lsi + 8)) + (l0 & ((1u << lsi) - 1u));
    for (int idx = tid; idx < 4096; idx += 256) {
        int b = idx & 15;
        int j = idx >> 4;
        sm[j * 17 + (b ^ (j >> 4))] = in[basei + b + ((unsigned)j << lsi)];
    }
    __syncthreads();

    const float scale = INV ? (1.0f / 256.0f) : 1.0f;
    const float insgn = (lane & 1) ? -1.0f : 1.0f;
    const int k1tab[8] = {0, 4, 2, 6, 1, 5, 3, 7};
    const int p = (int)(__brev((unsigned)lane) >> 27);
#pragma unroll
    for (int c = 0; c < 2; c++) {
        const int line = warp + 8 * c;
        float2 x[8];
#pragma unroll
        for (int r = 0; r < 8; r++) {
            int j = r * 32 + lane;
            float2 v = sm[j * 17 + (line ^ (j >> 4))];
            x[r] = make_float2(v.x * insgn, v.y * insgn);
        }
        fft_core<SIGN>(x, lane, tw);
#pragma unroll
        for (int r = 0; r < 8; r++) {
            int k = k1tab[r] + 8 * p;
            float sg = ((r >> 2) & 1) ? -scale : scale;
            sm[k * 17 + (line ^ (k >> 4))] = make_float2(x[r].x * sg, x[r].y * sg);
        }
    }
    __syncthreads();

    if (TRANSP) {
        const unsigned baseo = l0 << 8;
        for (int idx = tid; idx < 4096; idx += 256) {
            int b = idx >> 8;
            int k = idx & 255;
            out[baseo + ((unsigned)b << 8) + k] = sm[k * 17 + (b ^ (k >> 4))];
        }
    } else {
        for (int idx = tid; idx < 4096; idx += 256) {
            int b = idx & 15;
            int k = idx >> 4;
            out[basei + b + ((unsigned)k << lsi)] = sm[k * 17 + (b ^ (k >> 4))];
        }
    }
}

// ---------------------------------------------------------------------------
// Fused Fourier-slice sampling + centered inverse FFT over iv.
// Warp owns line (m, iu); lane r-loop walks iv = r*32+lane (z-contiguous
// gathers). Output T[m][iu][ka] contiguous.
// ---------------------------------------------------------------------------
__global__ void __launch_bounds__(256) sample_fft_kernel(const float2* __restrict__ F,
                                                         const float* __restrict__ theta,
                                                         const float* __restrict__ tilt,
                                                         float2* __restrict__ T) {
    __shared__ float2 sm[8][288];
    __shared__ float2 tw[256];
    const int tid  = threadIdx.x;
    const int warp = tid >> 5;
    const int lane = tid & 31;

    {
        float s, c;
        sincospif((float)tid * (1.0f / 128.0f), &s, &c);
        tw[tid] = make_float2(c, s);  // SIGN = +1 (inverse)
    }
    __syncthreads();

    const int lid = blockIdx.x * 8 + warp;
    const int m  = lid >> 8;
    const int iu = lid & 255;

    float st, ct;
    sincosf(theta[m], &st, &ct);
    float sp, cp;
    sincosf(*tilt, &sp, &cp);

    const float u = (float)(iu - 128);
    const float evx = -st * cp, evy = ct * cp, evz = sp;
    const float bx = u * ct + 128.0f;
    const float by = u * st + 128.0f;
    const float bz = 128.0f;

    float2 x[8];
    const float insgn = (lane & 1) ? -1.0f : 1.0f;
#pragma unroll
    for (int r = 0; r < 8; r++) {
        float v = (float)(r * 32 + lane - 128);
        float px = fmaf(v, evx, bx);
        float py = fmaf(v, evy, by);
        float pz = fmaf(v, evz, bz);

        float fx0 = floorf(px), fy0 = floorf(py), fz0 = floorf(pz);
        float fx = px - fx0, fy = py - fy0, fz = pz - fz0;
        int x0 = (int)fx0, y0 = (int)fy0, z0 = (int)fz0;

        float2 acc = make_float2(0.0f, 0.0f);
#pragma unroll
        for (int dx = 0; dx < 2; dx++) {
            int X = x0 + dx;
            float wx = dx ? fx : (1.0f - fx);
#pragma unroll
            for (int dy = 0; dy < 2; dy++) {
                int Y = y0 + dy;
                float wy = wx * (dy ? fy : (1.0f - fy));
#pragma unroll
                for (int dz = 0; dz < 2; dz++) {
                    int Z = z0 + dz;
                    float wz = wy * (dz ? fz : (1.0f - fz));
                    if ((unsigned)X < 256u && (unsigned)Y < 256u && (unsigned)Z < 256u) {
                        unsigned off = ((unsigned)X << 16) + ((unsigned)Y << 8) + (unsigned)Z;
                        float2 val = __ldg(&F[off]);
                        acc.x += wz * val.x;
                        acc.y += wz * val.y;
                    }
                }
            }
        }
        x[r] = make_float2(acc.x * insgn, acc.y * insgn);
    }

    fft_core<1>(x, lane, tw);

    const float scale = 1.0f / 256.0f;
    const int k1tab[8] = {0, 4, 2, 6, 1, 5, 3, 7};
    const int p = (int)(__brev((unsigned)lane) >> 27);
#pragma unroll
    for (int r = 0; r < 8; r++) {
        int k = k1tab[r] + 8 * p;
        float sg = ((r >> 2) & 1) ? -scale : scale;
        sm[warp][PIDX(k)] = make_float2(x[r].x * sg, x[r].y * sg);
    }
    __syncthreads();
    const unsigned base = blockIdx.x * 2048u;
    for (int idx = tid; idx < 2048; idx += 256)
        T[base + idx] = sm[idx >> 8][PIDX(idx & 255)];
}

// ---------------------------------------------------------------------------
extern "C" void kernel_launch(void* const* d_in, const int* in_sizes, int n_in,
                              void* d_out, int out_size) {
    const float2* w     = (const float2*)d_in[0];   // (256,256,256,2) f32
    const float*  theta = (const float*)d_in[1];    // (180,)
    const float*  tilt  = (const float*)d_in[2];    // scalar
    float2* out = (float2*)d_out;                   // (180,256,256,2) f32

    float2 *F, *S;
    cudaGetSymbolAddress((void**)&F, g_F);
    cudaGetSymbolAddress((void**)&S, g_S);

    // Forward centered 3D FFT: z (contig), y (stride 256), x (stride 65536).
    fft256c<-1, false><<<8192, 256>>>(w, F);
    fft256s<-1, false, true, false><<<4096, 256>>>(F, F, 8, tilt);
    fft256s<-1, false, true, false><<<4096, 256>>>(F, F, 16, tilt);

    // Fused slice sampling + inverse FFT over iv -> T[m][iu][ka]
    sample_fft_kernel<<<(MANG * 256) / 8, 256>>>(F, theta, tilt, S);

    // Inverse FFT over iu (stride 256 in T), transposed store -> out[m][ka][ku]
    fft256s<1, true, false, true><<<(MANG * 256) / 16, 256>>>(S, out, 8, nullptr);
}

// round 4
// speedup vs baseline: 2.5985x; 1.2462x over previous
#include <cuda_runtime.h>

#define NV 256
#define MANG 180
#define PIDX(j) ((j) + ((j) >> 3))

// Scratch (static device globals — no runtime allocation)
__device__ float2 g_F[NV * NV * NV];        // ping buffer
__device__ float2 g_F2[NV * NV * NV];       // pong buffer
__device__ float2 g_S[MANG * NV * NV];      // slice FFT intermediate T[m][iu][ka]

__device__ __forceinline__ float2 cmulf(float2 a, float2 b) {
    return make_float2(a.x * b.x - a.y * b.y, a.x * b.y + a.y * b.x);
}

// ---------------------------------------------------------------------------
// 256-pt FFT core: 8 regs/lane. radix-2^3 in regs + twiddle + radix-32 shuffle.
// On exit reg r, lane holds bin k = brev3(r) + 8*brev5(lane).
// tw[t] = e^{SIGN*i*pi*t/128}.
// ---------------------------------------------------------------------------
template <int SIGN>
__device__ __forceinline__ void fft_core(float2 x[8], int lane, const float2* tw) {
    const float SG = (float)SIGN;
    const float C7 = 0.70710678118654752f;
#define BTF(A, B, TR, TI)                                          \
    {                                                              \
        float dr = (A).x - (B).x, di = (A).y - (B).y;              \
        (A).x += (B).x; (A).y += (B).y;                            \
        (B).x = dr * (TR) - di * (TI);                             \
        (B).y = dr * (TI) + di * (TR);                             \
    }
    BTF(x[0], x[4], 1.0f, 0.0f);
    BTF(x[1], x[5], C7, SG * C7);
    BTF(x[2], x[6], 0.0f, SG);
    BTF(x[3], x[7], -C7, SG * C7);
    BTF(x[0], x[2], 1.0f, 0.0f);
    BTF(x[1], x[3], 0.0f, SG);
    BTF(x[4], x[6], 1.0f, 0.0f);
    BTF(x[5], x[7], 0.0f, SG);
    BTF(x[0], x[1], 1.0f, 0.0f);
    BTF(x[2], x[3], 1.0f, 0.0f);
    BTF(x[4], x[5], 1.0f, 0.0f);
    BTF(x[6], x[7], 1.0f, 0.0f);
#undef BTF
    const int k1tab[8] = {0, 4, 2, 6, 1, 5, 3, 7};
#pragma unroll
    for (int r = 1; r < 8; r++)
        x[r] = cmulf(x[r], tw[(lane * k1tab[r]) & 255]);
#pragma unroll
    for (int s = 4; s >= 0; s--) {
        const int h = 1 << s;
        const int j = lane & (h - 1);
        const float2 w = tw[j << (7 - s)];
        const bool hi = (lane & h) != 0;
#pragma unroll
        for (int r = 0; r < 8; r++) {
            float2 o;
            o.x = __shfl_xor_sync(0xffffffffu, x[r].x, h);
            o.y = __shfl_xor_sync(0xffffffffu, x[r].y, h);
            if (hi) {
                float2 d = make_float2(o.x - x[r].x, o.y - x[r].y);
                x[r] = cmulf(d, w);
            } else {
                x[r].x += o.x;
                x[r].y += o.y;
            }
        }
    }
}

// ---------------------------------------------------------------------------
// Contiguous-axis batched centered FFT: 8 lines/block, float4 gmem staging.
// ---------------------------------------------------------------------------
template <int SIGN, bool INV>
__global__ void __launch_bounds__(256) fft256c(const float2* __restrict__ in,
                                               float2* __restrict__ out) {
    __shared__ float2 sm[8][288];
    __shared__ float2 tw[256];
    const int tid  = threadIdx.x;
    const int warp = tid >> 5;
    const int lane = tid & 31;
    const unsigned base = blockIdx.x * 2048u;

    {
        float s, c;
        sincospif((float)tid * (1.0f / 128.0f), &s, &c);
        tw[tid] = make_float2(c, (float)SIGN * s);
    }
    {
        const float4* in4 = (const float4*)(in + base);
#pragma unroll
        for (int idx = tid; idx < 1024; idx += 256) {
            float4 v = in4[idx];
            int line = idx >> 7;
            int j = (idx & 127) * 2;
            sm[line][PIDX(j)]     = make_float2(v.x, v.y);
            sm[line][PIDX(j + 1)] = make_float2(v.z, v.w);
        }
    }
    __syncthreads();

    float2 x[8];
    const float insgn = (lane & 1) ? -1.0f : 1.0f;
#pragma unroll
    for (int r = 0; r < 8; r++) {
        float2 v = sm[warp][PIDX(r * 32 + lane)];
        x[r] = make_float2(v.x * insgn, v.y * insgn);
    }
    fft_core<SIGN>(x, lane, tw);

    const float scale = INV ? (1.0f / 256.0f) : 1.0f;
    const int k1tab[8] = {0, 4, 2, 6, 1, 5, 3, 7};
    const int p = (int)(__brev((unsigned)lane) >> 27);
#pragma unroll
    for (int r = 0; r < 8; r++) {
        int k = k1tab[r] + 8 * p;
        float sg = ((r >> 2) & 1) ? -scale : scale;
        sm[warp][PIDX(k)] = make_float2(x[r].x * sg, x[r].y * sg);
    }
    __syncthreads();
    {
        float4* out4 = (float4*)(out + base);
#pragma unroll
        for (int idx = tid; idx < 1024; idx += 256) {
            int line = idx >> 7;
            int k = (idx & 127) * 2;
            float2 a = sm[line][PIDX(k)];
            float2 b = sm[line][PIDX(k + 1)];
            out4[idx] = make_float4(a.x, a.y, b.x, b.y);
        }
    }
}

// ---------------------------------------------------------------------------
// Strided-axis batched centered FFT: 16 lines/block, float4 gmem staging.
// Shared layout idx(j,b) = j*17 + (b ^ (j>>4)).
// ZFILT: skip blocks whose z-range (z = line & 255) is never sampled.
// TRANSP: write lines contiguously (out[line*256 + k]) instead of strided.
// ---------------------------------------------------------------------------
template <int SIGN, bool INV, bool ZFILT, bool TRANSP>
__global__ void __launch_bounds__(256) fft256s(const float2* __restrict__ in,
                                               float2* __restrict__ out,
                                               int lsi, const float* tilt) {
    __shared__ float2 sm[256 * 17];
    __shared__ float2 tw[256];
    const int tid  = threadIdx.x;
    const int warp = tid >> 5;
    const int lane = tid & 31;
    const unsigned l0 = blockIdx.x * 16u;

    if (ZFILT) {
        float a = 128.0f * fabsf(sinf(*tilt));
        int zlo = (int)floorf(126.0f - a);
        int zhi = (int)ceilf(130.0f + a);
        int z0 = (int)(l0 & 255u);
        if (z0 > zhi || z0 + 15 < zlo) return;
    }

    {
        float s, c;
        sincospif((float)tid * (1.0f / 128.0f), &s, &c);
        tw[tid] = make_float2(c, (float)SIGN * s);
    }

    const unsigned basei = ((l0 >> lsi) << (lsi + 8)) + (l0 & ((1u << lsi) - 1u));
#pragma unroll
    for (int idx = tid; idx < 2048; idx += 256) {
        int bp = idx & 7;
        int j  = idx >> 3;
        int b  = 2 * bp;
        float4 v = *(const float4*)(in + basei + b + ((unsigned)j << lsi));
        int sw = (j >> 4);
        sm[j * 17 + (b ^ sw)]       = make_float2(v.x, v.y);
        sm[j * 17 + ((b + 1) ^ sw)] = make_float2(v.z, v.w);
    }
    __syncthreads();

    const float scale = INV ? (1.0f / 256.0f) : 1.0f;
    const float insgn = (lane & 1) ? -1.0f : 1.0f;
    const int k1tab[8] = {0, 4, 2, 6, 1, 5, 3, 7};
    const int p = (int)(__brev((unsigned)lane) >> 27);
#pragma unroll
    for (int c = 0; c < 2; c++) {
        const int line = warp + 8 * c;
        float2 x[8];
#pragma unroll
        for (int r = 0; r < 8; r++) {
            int j = r * 32 + lane;
            float2 v = sm[j * 17 + (line ^ (j >> 4))];
            x[r] = make_float2(v.x * insgn, v.y * insgn);
        }
        fft_core<SIGN>(x, lane, tw);
#pragma unroll
        for (int r = 0; r < 8; r++) {
            int k = k1tab[r] + 8 * p;
            float sg = ((r >> 2) & 1) ? -scale : scale;
            sm[k * 17 + (line ^ (k >> 4))] = make_float2(x[r].x * sg, x[r].y * sg);
        }
    }
    __syncthreads();

    if (TRANSP) {
        const unsigned baseo = l0 << 8;
#pragma unroll
        for (int idx = tid; idx < 2048; idx += 256) {
            int kp = idx & 127;
            int b  = idx >> 7;
            int k  = 2 * kp;
            int sw = (k >> 4);
            float2 a = sm[k * 17 + (b ^ sw)];
            float2 c = sm[(k + 1) * 17 + (b ^ sw)];
            *(float4*)(out + baseo + ((unsigned)b << 8) + k) = make_float4(a.x, a.y, c.x, c.y);
        }
    } else {
#pragma unroll
        for (int idx = tid; idx < 2048; idx += 256) {
            int bp = idx & 7;
            int k  = idx >> 3;
            int b  = 2 * bp;
            int sw = (k >> 4);
            float2 a = sm[k * 17 + (b ^ sw)];
            float2 c = sm[k * 17 + ((b + 1) ^ sw)];
            *(float4*)(out + basei + b + ((unsigned)k << lsi)) = make_float4(a.x, a.y, c.x, c.y);
        }
    }
}

// ---------------------------------------------------------------------------
// Fused Fourier-slice sampling + centered inverse FFT over iv.
// Warp owns line (m, iu); lanes walk iv (z-contiguous gathers).
// Interior fast path: one stencil bounds test -> 8 unpredicated __ldg.
// ---------------------------------------------------------------------------
__global__ void __launch_bounds__(256) sample_fft_kernel(const float2* __restrict__ F,
                                                         const float* __restrict__ theta,
                                                         const float* __restrict__ tilt,
                                                         float2* __restrict__ T) {
    __shared__ float2 sm[8][288];
    __shared__ float2 tw[256];
    const int tid  = threadIdx.x;
    const int warp = tid >> 5;
    const int lane = tid & 31;

    {
        float s, c;
        sincospif((float)tid * (1.0f / 128.0f), &s, &c);
        tw[tid] = make_float2(c, s);  // SIGN = +1 (inverse)
    }
    __syncthreads();

    const int lid = blockIdx.x * 8 + warp;
    const int m  = lid >> 8;
    const int iu = lid & 255;

    float st, ct;
    sincosf(theta[m], &st, &ct);
    float sp, cp;
    sincosf(*tilt, &sp, &cp);

    const float u = (float)(iu - 128);
    const float evx = -st * cp, evy = ct * cp, evz = sp;
    const float bx = u * ct + 128.0f;
    const float by = u * st + 128.0f;
    const float bz = 128.0f;

    float2 x[8];
    const float insgn = (lane & 1) ? -1.0f : 1.0f;
#pragma unroll
    for (int r = 0; r < 8; r++) {
        float v = (float)(r * 32 + lane - 128);
        float px = fmaf(v, evx, bx);
        float py = fmaf(v, evy, by);
        float pz = fmaf(v, evz, bz);

        float fx0 = floorf(px), fy0 = floorf(py), fz0 = floorf(pz);
        float fx = px - fx0, fy = py - fy0, fz = pz - fz0;
        int x0 = (int)fx0, y0 = (int)fy0, z0 = (int)fz0;

        float2 acc = make_float2(0.0f, 0.0f);
        bool interior = ((unsigned)x0 <= 254u) && ((unsigned)y0 <= 254u) && ((unsigned)z0 <= 254u);
        bool anyhit = (x0 >= -1) && (x0 <= 255) && (y0 >= -1) && (y0 <= 255) &&
                      (z0 >= -1) && (z0 <= 255);
        if (interior) {
            const float2* ptr = F + (((unsigned)x0 << 16) + ((unsigned)y0 << 8) + (unsigned)z0);
            float2 c000 = __ldg(ptr);
            float2 c001 = __ldg(ptr + 1);
            float2 c010 = __ldg(ptr + 256);
            float2 c011 = __ldg(ptr + 257);
            float2 c100 = __ldg(ptr + 65536);
            float2 c101 = __ldg(ptr + 65537);
            float2 c110 = __ldg(ptr + 65792);
            float2 c111 = __ldg(ptr + 65793);
            float gx = 1.0f - fx, gy = 1.0f - fy, gz = 1.0f - fz;
            float w00 = gx * gy, w01 = gx * fy, w10 = fx * gy, w11 = fx * fy;
            float w000 = w00 * gz, w001 = w00 * fz;
            float w010 = w01 * gz, w011 = w01 * fz;
            float w100 = w10 * gz, w101 = w10 * fz;
            float w110 = w11 * gz, w111 = w11 * fz;
            acc.x = w000 * c000.x + w001 * c001.x + w010 * c010.x + w011 * c011.x +
                    w100 * c100.x + w101 * c101.x + w110 * c110.x + w111 * c111.x;
            acc.y = w000 * c000.y + w001 * c001.y + w010 * c010.y + w011 * c011.y +
                    w100 * c100.y + w101 * c101.y + w110 * c110.y + w111 * c111.y;
        } else if (anyhit) {
#pragma unroll
            for (int dx = 0; dx < 2; dx++) {
                int X = x0 + dx;
                float wx = dx ? fx : (1.0f - fx);
#pragma unroll
                for (int dy = 0; dy < 2; dy++) {
                    int Y = y0 + dy;
                    float wy = wx * (dy ? fy : (1.0f - fy));
#pragma unroll
                    for (int dz = 0; dz < 2; dz++) {
                        int Z = z0 + dz;
                        float wz = wy * (dz ? fz : (1.0f - fz));
                        if ((unsigned)X < 256u && (unsigned)Y < 256u && (unsigned)Z < 256u) {
                            unsigned off = ((unsigned)X << 16) + ((unsigned)Y << 8) + (unsigned)Z;
                            float2 val = __ldg(&F[off]);
                            acc.x += wz * val.x;
                            acc.y += wz * val.y;
                        }
                    }
                }
            }
        }
        x[r] = make_float2(acc.x * insgn, acc.y * insgn);
    }

    fft_core<1>(x, lane, tw);

    const float scale = 1.0f / 256.0f;
    const int k1tab[8] = {0, 4, 2, 6, 1, 5, 3, 7};
    const int p = (int)(__brev((unsigned)lane) >> 27);
#pragma unroll
    for (int r = 0; r < 8; r++) {
        int k = k1tab[r] + 8 * p;
        float sg = ((r >> 2) & 1) ? -scale : scale;
        sm[warp][PIDX(k)] = make_float2(x[r].x * sg, x[r].y * sg);
    }
    __syncthreads();
    {
        const unsigned base = blockIdx.x * 2048u;
        float4* T4 = (float4*)(T + base);
#pragma unroll
        for (int idx = tid; idx < 1024; idx += 256) {
            int line = idx >> 7;
            int k = (idx & 127) * 2;
            float2 a = sm[line][PIDX(k)];
            float2 b = sm[line][PIDX(k + 1)];
            T4[idx] = make_float4(a.x, a.y, b.x, b.y);
        }
    }
}

// ---------------------------------------------------------------------------
extern "C" void kernel_launch(void* const* d_in, const int* in_sizes, int n_in,
                              void* d_out, int out_size) {
    const float2* w     = (const float2*)d_in[0];   // (256,256,256,2) f32
    const float*  theta = (const float*)d_in[1];    // (180,)
    const float*  tilt  = (const float*)d_in[2];    // scalar
    float2* out = (float2*)d_out;                   // (180,256,256,2) f32

    float2 *F, *F2, *S;
    cudaGetSymbolAddress((void**)&F, g_F);
    cudaGetSymbolAddress((void**)&F2, g_F2);
    cudaGetSymbolAddress((void**)&S, g_S);

    // Forward centered 3D FFT (ping-pong): z (contig), y (s=256), x (s=65536)
    fft256c<-1, false><<<8192, 256>>>(w, F);
    fft256s<-1, false, true, false><<<4096, 256>>>(F, F2, 8, tilt);
    fft256s<-1, false, true, false><<<4096, 256>>>(F2, F, 16, tilt);

    // Fused slice sampling + inverse FFT over iv -> T[m][iu][ka]
    sample_fft_kernel<<<(MANG * 256) / 8, 256>>>(F, theta, tilt, S);

    // Inverse FFT over iu (stride 256 in T), transposed store -> out[m][ka][ku]
    fft256s<1, true, false, true><<<(MANG * 256) / 16, 256>>>(S, out, 8, nullptr);
}

// round 5
// speedup vs baseline: 3.0088x; 1.1579x over previous
#include <cuda_runtime.h>
#include <cuda_fp16.h>

#define NV 256
#define MANG 180
#define PIDX(j) ((j) + ((j) >> 3))

// Scratch (static device globals — no runtime allocation). fp16 complex.
__device__ __half2 g_Fh[NV * NV * NV];      // ping (67 MB)
__device__ __half2 g_F2h[NV * NV * NV];     // pong (67 MB)
__device__ __half2 g_Sh[MANG * NV * NV];    // slice intermediate T[m][iu][ka]

__device__ __forceinline__ float2 cmulf(float2 a, float2 b) {
    return make_float2(a.x * b.x - a.y * b.y, a.x * b.y + a.y * b.x);
}
__device__ __forceinline__ float2 toF2(float2 v) { return v; }
__device__ __forceinline__ float2 toF2(__half2 h) { return __half22float2(h); }
__device__ __forceinline__ void fromF2(float2 v, float2& o) { o = v; }
__device__ __forceinline__ void fromF2(float2 v, __half2& o) { o = __floats2half2_rn(v.x, v.y); }

// ---------------------------------------------------------------------------
// 256-pt FFT core: 8 regs/lane. radix-2^3 in regs + twiddle + radix-32 shuffle.
// On exit reg r, lane holds bin k = brev3(r) + 8*brev5(lane).
// ---------------------------------------------------------------------------
template <int SIGN>
__device__ __forceinline__ void fft_core(float2 x[8], int lane, const float2* tw) {
    const float SG = (float)SIGN;
    const float C7 = 0.70710678118654752f;
#define BTF(A, B, TR, TI)                                          \
    {                                                              \
        float dr = (A).x - (B).x, di = (A).y - (B).y;              \
        (A).x += (B).x; (A).y += (B).y;                            \
        (B).x = dr * (TR) - di * (TI);                             \
        (B).y = dr * (TI) + di * (TR);                             \
    }
    BTF(x[0], x[4], 1.0f, 0.0f);
    BTF(x[1], x[5], C7, SG * C7);
    BTF(x[2], x[6], 0.0f, SG);
    BTF(x[3], x[7], -C7, SG * C7);
    BTF(x[0], x[2], 1.0f, 0.0f);
    BTF(x[1], x[3], 0.0f, SG);
    BTF(x[4], x[6], 1.0f, 0.0f);
    BTF(x[5], x[7], 0.0f, SG);
    BTF(x[0], x[1], 1.0f, 0.0f);
    BTF(x[2], x[3], 1.0f, 0.0f);
    BTF(x[4], x[5], 1.0f, 0.0f);
    BTF(x[6], x[7], 1.0f, 0.0f);
#undef BTF
    const int k1tab[8] = {0, 4, 2, 6, 1, 5, 3, 7};
#pragma unroll
    for (int r = 1; r < 8; r++)
        x[r] = cmulf(x[r], tw[(lane * k1tab[r]) & 255]);
#pragma unroll
    for (int s = 4; s >= 0; s--) {
        const int h = 1 << s;
        const int j = lane & (h - 1);
        const float2 w = tw[j << (7 - s)];
        const bool hi = (lane & h) != 0;
#pragma unroll
        for (int r = 0; r < 8; r++) {
            float2 o;
            o.x = __shfl_xor_sync(0xffffffffu, x[r].x, h);
            o.y = __shfl_xor_sync(0xffffffffu, x[r].y, h);
            if (hi) {
                float2 d = make_float2(o.x - x[r].x, o.y - x[r].y);
                x[r] = cmulf(d, w);
            } else {
                x[r].x += o.x;
                x[r].y += o.y;
            }
        }
    }
}

// ---------------------------------------------------------------------------
// Pass 1: contiguous z-axis forward FFT. f32 in (float4 vec loads), fp16 out.
// Store filter: only z in the sampled band [zlo, zhi] (from tilt) is written.
// ---------------------------------------------------------------------------
__global__ void __launch_bounds__(256) fft256_p1(const float2* __restrict__ in,
                                                 __half2* __restrict__ out,
                                                 const float* tilt) {
    __shared__ float2 sm[8][288];
    __shared__ float2 tw[256];
    const int tid  = threadIdx.x;
    const int warp = tid >> 5;
    const int lane = tid & 31;
    const unsigned base = blockIdx.x * 2048u;

    float a = 128.0f * fabsf(sinf(*tilt));
    const int zlo = (int)floorf(126.0f - a);
    const int zhi = (int)ceilf(130.0f + a);

    {
        float s, c;
        sincospif((float)tid * (1.0f / 128.0f), &s, &c);
        tw[tid] = make_float2(c, -s);   // SIGN = -1
    }
    {
        const float4* in4 = (const float4*)(in + base);
#pragma unroll
        for (int idx = tid; idx < 1024; idx += 256) {
            float4 v = in4[idx];
            int line = idx >> 7;
            int j = (idx & 127) * 2;
            sm[line][PIDX(j)]     = make_float2(v.x, v.y);
            sm[line][PIDX(j + 1)] = make_float2(v.z, v.w);
        }
    }
    __syncthreads();

    float2 x[8];
    const float insgn = (lane & 1) ? -1.0f : 1.0f;
#pragma unroll
    for (int r = 0; r < 8; r++) {
        float2 v = sm[warp][PIDX(r * 32 + lane)];
        x[r] = make_float2(v.x * insgn, v.y * insgn);
    }
    fft_core<-1>(x, lane, tw);

    const int k1tab[8] = {0, 4, 2, 6, 1, 5, 3, 7};
    const int p = (int)(__brev((unsigned)lane) >> 27);
#pragma unroll
    for (int r = 0; r < 8; r++) {
        int k = k1tab[r] + 8 * p;
        float sg = ((r >> 2) & 1) ? -1.0f : 1.0f;
        sm[warp][PIDX(k)] = make_float2(x[r].x * sg, x[r].y * sg);
    }
    __syncthreads();
#pragma unroll
    for (int idx = tid; idx < 2048; idx += 256) {
        int k = idx & 255;
        if (k >= zlo && k <= zhi)
            out[base + idx] = __floats2half2_rn(sm[idx >> 8][PIDX(k)].x,
                                                sm[idx >> 8][PIDX(k)].y);
    }
}

// ---------------------------------------------------------------------------
// Strided-axis batched centered FFT: 16 lines/block, generic in/out types.
// Shared layout idx(j,b) = j*17 + (b ^ (j>>4)).
// ZFILT: skip blocks whose z-range (z = line & 255) is outside sampled band.
// TRANSP: write lines contiguously (out[line*256 + k]).
// ---------------------------------------------------------------------------
template <int SIGN, bool INV, bool ZFILT, bool TRANSP, class TI, class TO>
__global__ void __launch_bounds__(256) fft256s(const TI* __restrict__ in,
                                               TO* __restrict__ out,
                                               int lsi, const float* tilt) {
    __shared__ float2 sm[256 * 17];
    __shared__ float2 tw[256];
    const int tid  = threadIdx.x;
    const int warp = tid >> 5;
    const int lane = tid & 31;
    const unsigned l0 = blockIdx.x * 16u;

    if (ZFILT) {
        float a = 128.0f * fabsf(sinf(*tilt));
        int zlo = (int)floorf(126.0f - a);
        int zhi = (int)ceilf(130.0f + a);
        int z0 = (int)(l0 & 255u);
        if (z0 > zhi || z0 + 15 < zlo) return;
    }

    {
        float s, c;
        sincospif((float)tid * (1.0f / 128.0f), &s, &c);
        tw[tid] = make_float2(c, (float)SIGN * s);
    }

    const unsigned basei = ((l0 >> lsi) << (lsi + 8)) + (l0 & ((1u << lsi) - 1u));
#pragma unroll
    for (int idx = tid; idx < 4096; idx += 256) {
        int b = idx & 15;
        int j = idx >> 4;
        sm[j * 17 + (b ^ (j >> 4))] = toF2(in[basei + b + ((unsigned)j << lsi)]);
    }
    __syncthreads();

    const float scale = INV ? (1.0f / 256.0f) : 1.0f;
    const float insgn = (lane & 1) ? -1.0f : 1.0f;
    const int k1tab[8] = {0, 4, 2, 6, 1, 5, 3, 7};
    const int p = (int)(__brev((unsigned)lane) >> 27);
#pragma unroll
    for (int c = 0; c < 2; c++) {
        const int line = warp + 8 * c;
        float2 x[8];
#pragma unroll
        for (int r = 0; r < 8; r++) {
            int j = r * 32 + lane;
            float2 v = sm[j * 17 + (line ^ (j >> 4))];
            x[r] = make_float2(v.x * insgn, v.y * insgn);
        }
        fft_core<SIGN>(x, lane, tw);
#pragma unroll
        for (int r = 0; r < 8; r++) {
            int k = k1tab[r] + 8 * p;
            float sg = ((r >> 2) & 1) ? -scale : scale;
            sm[k * 17 + (line ^ (k >> 4))] = make_float2(x[r].x * sg, x[r].y * sg);
        }
    }
    __syncthreads();

    if (TRANSP) {
        const unsigned baseo = l0 << 8;
#pragma unroll
        for (int idx = tid; idx < 4096; idx += 256) {
            int b = idx >> 8;
            int k = idx & 255;
            fromF2(sm[k * 17 + (b ^ (k >> 4))], out[baseo + ((unsigned)b << 8) + k]);
        }
    } else {
#pragma unroll
        for (int idx = tid; idx < 4096; idx += 256) {
            int b = idx & 15;
            int k = idx >> 4;
            fromF2(sm[k * 17 + (b ^ (k >> 4))], out[basei + b + ((unsigned)k << lsi)]);
        }
    }
}

// ---------------------------------------------------------------------------
// Fused Fourier-slice sampling + centered inverse FFT over iv.
// Warp owns line (m, iu); lanes walk iv (z-contiguous gathers). fp16 F and T.
// ---------------------------------------------------------------------------
__global__ void __launch_bounds__(256) sample_fft_kernel(const __half2* __restrict__ F,
                                                         const float* __restrict__ theta,
                                                         const float* __restrict__ tilt,
                                                         __half2* __restrict__ T) {
    __shared__ float2 sm[8][288];
    __shared__ float2 tw[256];
    const int tid  = threadIdx.x;
    const int warp = tid >> 5;
    const int lane = tid & 31;

    {
        float s, c;
        sincospif((float)tid * (1.0f / 128.0f), &s, &c);
        tw[tid] = make_float2(c, s);  // SIGN = +1 (inverse)
    }
    __syncthreads();

    const int lid = blockIdx.x * 8 + warp;
    const int m  = lid >> 8;
    const int iu = lid & 255;

    float st, ct;
    sincosf(theta[m], &st, &ct);
    float sp, cp;
    sincosf(*tilt, &sp, &cp);

    const float u = (float)(iu - 128);
    const float evx = -st * cp, evy = ct * cp, evz = sp;
    const float bx = u * ct + 128.0f;
    const float by = u * st + 128.0f;
    const float bz = 128.0f;

    float2 x[8];
    const float insgn = (lane & 1) ? -1.0f : 1.0f;
#pragma unroll
    for (int r = 0; r < 8; r++) {
        float v = (float)(r * 32 + lane - 128);
        float px = fmaf(v, evx, bx);
        float py = fmaf(v, evy, by);
        float pz = fmaf(v, evz, bz);

        float fx0 = floorf(px), fy0 = floorf(py), fz0 = floorf(pz);
        float fx = px - fx0, fy = py - fy0, fz = pz - fz0;
        int x0 = (int)fx0, y0 = (int)fy0, z0 = (int)fz0;

        float2 acc = make_float2(0.0f, 0.0f);
        bool interior = ((unsigned)x0 <= 254u) && ((unsigned)y0 <= 254u) && ((unsigned)z0 <= 254u);
        bool anyhit = (x0 >= -1) && (x0 <= 255) && (y0 >= -1) && (y0 <= 255) &&
                      (z0 >= -1) && (z0 <= 255);
        if (interior) {
            const __half2* ptr = F + (((unsigned)x0 << 16) + ((unsigned)y0 << 8) + (unsigned)z0);
            float2 c000 = toF2(__ldg(ptr));
            float2 c001 = toF2(__ldg(ptr + 1));
            float2 c010 = toF2(__ldg(ptr + 256));
            float2 c011 = toF2(__ldg(ptr + 257));
            float2 c100 = toF2(__ldg(ptr + 65536));
            float2 c101 = toF2(__ldg(ptr + 65537));
            float2 c110 = toF2(__ldg(ptr + 65792));
            float2 c111 = toF2(__ldg(ptr + 65793));
            float gx = 1.0f - fx, gy = 1.0f - fy, gz = 1.0f - fz;
            float w00 = gx * gy, w01 = gx * fy, w10 = fx * gy, w11 = fx * fy;
            float w000 = w00 * gz, w001 = w00 * fz;
            float w010 = w01 * gz, w011 = w01 * fz;
            float w100 = w10 * gz, w101 = w10 * fz;
            float w110 = w11 * gz, w111 = w11 * fz;
            acc.x = w000 * c000.x + w001 * c001.x + w010 * c010.x + w011 * c011.x +
                    w100 * c100.x + w101 * c101.x + w110 * c110.x + w111 * c111.x;
            acc.y = w000 * c000.y + w001 * c001.y + w010 * c010.y + w011 * c011.y +
                    w100 * c100.y + w101 * c101.y + w110 * c110.y + w111 * c111.y;
        } else if (anyhit) {
#pragma unroll
            for (int dx = 0; dx < 2; dx++) {
                int X = x0 + dx;
                float wx = dx ? fx : (1.0f - fx);
#pragma unroll
                for (int dy = 0; dy < 2; dy++) {
                    int Y = y0 + dy;
                    float wy = wx * (dy ? fy : (1.0f - fy));
#pragma unroll
                    for (int dz = 0; dz < 2; dz++) {
                        int Z = z0 + dz;
                        float wz = wy * (dz ? fz : (1.0f - fz));
                        if ((unsigned)X < 256u && (unsigned)Y < 256u && (unsigned)Z < 256u) {
                            unsigned off = ((unsigned)X << 16) + ((unsigned)Y << 8) + (unsigned)Z;
                            float2 val = toF2(__ldg(&F[off]));
                            acc.x += wz * val.x;
                            acc.y += wz * val.y;
                        }
                    }
                }
            }
        }
        x[r] = make_float2(acc.x * insgn, acc.y * insgn);
    }

    fft_core<1>(x, lane, tw);

    const float scale = 1.0f / 256.0f;
    const int k1tab[8] = {0, 4, 2, 6, 1, 5, 3, 7};
    const int p = (int)(__brev((unsigned)lane) >> 27);
#pragma unroll
    for (int r = 0; r < 8; r++) {
        int k = k1tab[r] + 8 * p;
        float sg = ((r >> 2) & 1) ? -scale : scale;
        sm[warp][PIDX(k)] = make_float2(x[r].x * sg, x[r].y * sg);
    }
    __syncthreads();
    {
        const unsigned base = blockIdx.x * 2048u;
#pragma unroll
        for (int idx = tid; idx < 2048; idx += 256) {
            float2 v = sm[idx >> 8][PIDX(idx & 255)];
            T[base + idx] = __floats2half2_rn(v.x, v.y);
        }
    }
}

// ---------------------------------------------------------------------------
extern "C" void kernel_launch(void* const* d_in, const int* in_sizes, int n_in,
                              void* d_out, int out_size) {
    const float2* w     = (const float2*)d_in[0];   // (256,256,256,2) f32
    const float*  theta = (const float*)d_in[1];    // (180,)
    const float*  tilt  = (const float*)d_in[2];    // scalar
    float2* out = (float2*)d_out;                   // (180,256,256,2) f32

    __half2 *F, *F2, *S;
    cudaGetSymbolAddress((void**)&F, g_Fh);
    cudaGetSymbolAddress((void**)&F2, g_F2h);
    cudaGetSymbolAddress((void**)&S, g_Sh);

    // Forward centered 3D FFT (ping-pong, fp16 intermediates):
    fft256_p1<<<8192, 256>>>(w, F, tilt);                                   // z
    fft256s<-1, false, true, false, __half2, __half2><<<4096, 256>>>(F, F2, 8, tilt);   // y
    fft256s<-1, false, true, false, __half2, __half2><<<4096, 256>>>(F2, F, 16, tilt);  // x

    // Fused slice sampling + inverse FFT over iv -> T[m][iu][ka] (fp16)
    sample_fft_kernel<<<(MANG * 256) / 8, 256>>>(F, theta, tilt, S);

    // Inverse FFT over iu (stride 256 in T), transposed store -> out (f32)
    fft256s<1, true, false, true, __half2, float2><<<(MANG * 256) / 16, 256>>>(S, out, 8, nullptr);
}